// round 2
// baseline (speedup 1.0000x reference)
#include <cuda_runtime.h>
#include <math.h>

#define TSEQ 2048
#define CDIM 2048
#define QKVD 3072
#define NHEAD 32
#define NGRP 8
#define HSZ 64

// scratch (no allocations allowed)
__device__ float g_qkv[TSEQ * QKVD];   // 24 MB
__device__ float g_y[TSEQ * CDIM];     // 16 MB

// ---------------------------------------------------------------------------
// NT GEMM: C[M,N] = A[M,K] * B[N,K]^T + bias[N]
// 128x128 block, BK=16, 256 threads, 8x8 micro-tile, transposed smem tiles.
// ---------------------------------------------------------------------------
template<int M, int N, int K>
__global__ void __launch_bounds__(256, 2) gemm_nt_bias(
    const float* __restrict__ A,
    const float* __restrict__ B,
    const float* __restrict__ bias,
    float* __restrict__ C)
{
    __shared__ float Ast[16][128];
    __shared__ float Bst[16][128];

    const int tid = threadIdx.x;
    const int tx  = tid & 15;
    const int ty  = tid >> 4;
    const int m0  = blockIdx.y * 128;
    const int n0  = blockIdx.x * 128;
    const int lrow = tid >> 1;          // 0..127
    const int lk   = (tid & 1) * 8;     // 0 or 8

    const float* Aptr = A + (size_t)(m0 + lrow) * K + lk;
    const float* Bptr = B + (size_t)(n0 + lrow) * K + lk;

    float acc[8][8];
#pragma unroll
    for (int i = 0; i < 8; ++i)
#pragma unroll
        for (int j = 0; j < 8; ++j) acc[i][j] = 0.f;

    for (int k0 = 0; k0 < K; k0 += 16) {
#pragma unroll
        for (int c = 0; c < 8; c += 4) {
            float4 av = *(const float4*)(Aptr + k0 + c);
            Ast[lk + c + 0][lrow] = av.x;
            Ast[lk + c + 1][lrow] = av.y;
            Ast[lk + c + 2][lrow] = av.z;
            Ast[lk + c + 3][lrow] = av.w;
            float4 bv = *(const float4*)(Bptr + k0 + c);
            Bst[lk + c + 0][lrow] = bv.x;
            Bst[lk + c + 1][lrow] = bv.y;
            Bst[lk + c + 2][lrow] = bv.z;
            Bst[lk + c + 3][lrow] = bv.w;
        }
        __syncthreads();
#pragma unroll
        for (int k = 0; k < 16; ++k) {
            float a[8], b[8];
            *(float4*)&a[0] = *(const float4*)&Ast[k][8 * ty];
            *(float4*)&a[4] = *(const float4*)&Ast[k][8 * ty + 4];
            *(float4*)&b[0] = *(const float4*)&Bst[k][8 * tx];
            *(float4*)&b[4] = *(const float4*)&Bst[k][8 * tx + 4];
#pragma unroll
            for (int i = 0; i < 8; ++i)
#pragma unroll
                for (int j = 0; j < 8; ++j)
                    acc[i][j] = fmaf(a[i], b[j], acc[i][j]);
        }
        __syncthreads();
    }

    const int n = n0 + 8 * tx;
    float bv[8];
#pragma unroll
    for (int j = 0; j < 8; ++j) bv[j] = bias[n + j];
#pragma unroll
    for (int i = 0; i < 8; ++i) {
        const int m = m0 + 8 * ty + i;
        float4 o0 = make_float4(acc[i][0] + bv[0], acc[i][1] + bv[1],
                                acc[i][2] + bv[2], acc[i][3] + bv[3]);
        float4 o1 = make_float4(acc[i][4] + bv[4], acc[i][5] + bv[5],
                                acc[i][6] + bv[6], acc[i][7] + bv[7]);
        *(float4*)&C[(size_t)m * N + n]     = o0;
        *(float4*)&C[(size_t)m * N + n + 4] = o1;
    }
}

// ---------------------------------------------------------------------------
// RoPE in-place on qkv[T, 3072]. 40 rope-heads per token (32 q + 8 k),
// rotate dims [0,16): out[d] = x1*cos[d] - x2*sin[d]; out[d+8] = x2*cos[d+8] + x1*sin[d+8]
// ---------------------------------------------------------------------------
__global__ void rope_kernel(float* __restrict__ qkv,
                            const float* __restrict__ cosb,
                            const float* __restrict__ sinb)
{
    const int idx = blockIdx.x * 256 + threadIdx.x;   // [0, TSEQ*320)
    if (idx >= TSEQ * 40 * 8) return;
    const int d  = idx & 7;
    const int r  = (idx >> 3) % 40;
    const int t  = idx / 320;
    int gg, ss;
    if (r < 32) { gg = r >> 2; ss = r & 3; }
    else        { gg = r - 32; ss = 4; }
    const int base = t * QKVD + gg * 384 + ss * 64;
    const float x1 = qkv[base + d];
    const float x2 = qkv[base + d + 8];
    const float c1 = cosb[t * 16 + d],     s1 = sinb[t * 16 + d];
    const float c2 = cosb[t * 16 + d + 8], s2 = sinb[t * 16 + d + 8];
    qkv[base + d]     = x1 * c1 - x2 * s1;
    qkv[base + d + 8] = x2 * c2 + x1 * s2;
}

// ---------------------------------------------------------------------------
// Flash attention, causal, fp32. 64x64 tiles, 256 threads (16x16), 4x4 micro.
// Q/K stored transposed [d][i] in smem; KP buffer reused to hold P[i][j].
// ---------------------------------------------------------------------------
__global__ void __launch_bounds__(256, 2) flash_kernel(
    const float* __restrict__ qkv, float* __restrict__ Y)
{
    __shared__ float Qts[64][64];   // [d][i]
    __shared__ float KP[64][64];    // Kt [d][j], then P [i][j]
    __shared__ float Vs[64][64];    // [j][d]

    const int h  = blockIdx.y;
    const int m0 = ((int)gridDim.x - 1 - (int)blockIdx.x) * 64;  // heavy tiles first
    const int gg = h >> 2;
    const int qoff = gg * 384 + (h & 3) * 64;
    const int koff = gg * 384 + 256;
    const int voff = gg * 384 + 320;

    const int tid = threadIdx.x;
    const int tx  = tid & 15;
    const int ty  = tid >> 4;
    const int lrow = tid >> 2;         // 0..63
    const int ld0  = (tid & 3) * 16;   // 0,16,32,48

    // load Q tile transposed
    {
        const float* qp = qkv + (size_t)(m0 + lrow) * QKVD + qoff + ld0;
#pragma unroll
        for (int c = 0; c < 4; ++c) {
            float4 v = *(const float4*)(qp + 4 * c);
            Qts[ld0 + 4 * c + 0][lrow] = v.x;
            Qts[ld0 + 4 * c + 1][lrow] = v.y;
            Qts[ld0 + 4 * c + 2][lrow] = v.z;
            Qts[ld0 + 4 * c + 3][lrow] = v.w;
        }
    }

    float mrow[4], lsum[4], acc[4][4];
#pragma unroll
    for (int i = 0; i < 4; ++i) {
        mrow[i] = -1e30f; lsum[i] = 0.f;
#pragma unroll
        for (int j = 0; j < 4; ++j) acc[i][j] = 0.f;
    }

    const float scale = 0.125f;   // 1/sqrt(64)

    for (int n0 = 0; n0 <= m0; n0 += 64) {
        __syncthreads();   // prior-iteration KP/Vs consumers done (also orders Q store)
        // load K (transposed) and V tiles
        {
            const float* kp = qkv + (size_t)(n0 + lrow) * QKVD + koff + ld0;
            const float* vp = qkv + (size_t)(n0 + lrow) * QKVD + voff + ld0;
#pragma unroll
            for (int c = 0; c < 4; ++c) {
                float4 kv = *(const float4*)(kp + 4 * c);
                KP[ld0 + 4 * c + 0][lrow] = kv.x;
                KP[ld0 + 4 * c + 1][lrow] = kv.y;
                KP[ld0 + 4 * c + 2][lrow] = kv.z;
                KP[ld0 + 4 * c + 3][lrow] = kv.w;
                float4 vv = *(const float4*)(vp + 4 * c);
                *(float4*)&Vs[lrow][ld0 + 4 * c] = vv;
            }
        }
        __syncthreads();

        // S = Q K^T (scaled)
        float S[4][4];
#pragma unroll
        for (int i = 0; i < 4; ++i)
#pragma unroll
            for (int j = 0; j < 4; ++j) S[i][j] = 0.f;

        for (int d = 0; d < 64; ++d) {
            float4 qa = *(const float4*)&Qts[d][4 * ty];
            float4 kb = *(const float4*)&KP[d][4 * tx];
            float a[4] = {qa.x, qa.y, qa.z, qa.w};
            float b[4] = {kb.x, kb.y, kb.z, kb.w};
#pragma unroll
            for (int i = 0; i < 4; ++i)
#pragma unroll
                for (int j = 0; j < 4; ++j)
                    S[i][j] = fmaf(a[i], b[j], S[i][j]);
        }

        const bool diag = (n0 == m0);
#pragma unroll
        for (int i = 0; i < 4; ++i)
#pragma unroll
            for (int j = 0; j < 4; ++j) {
                S[i][j] *= scale;
                if (diag && (4 * tx + j) > (4 * ty + i)) S[i][j] = -1e30f;
            }

        // online softmax (row owned by the 16 lanes sharing ty)
        float fac[4];
#pragma unroll
        for (int i = 0; i < 4; ++i) {
            float mx = fmaxf(fmaxf(S[i][0], S[i][1]), fmaxf(S[i][2], S[i][3]));
#pragma unroll
            for (int w = 1; w < 16; w <<= 1)
                mx = fmaxf(mx, __shfl_xor_sync(0xffffffffu, mx, w));
            const float mnew = fmaxf(mrow[i], mx);
            fac[i]  = __expf(mrow[i] - mnew);
            mrow[i] = mnew;
            float rs = 0.f;
#pragma unroll
            for (int j = 0; j < 4; ++j) {
                S[i][j] = __expf(S[i][j] - mnew);
                rs += S[i][j];
            }
#pragma unroll
            for (int w = 1; w < 16; w <<= 1)
                rs += __shfl_xor_sync(0xffffffffu, rs, w);
            lsum[i] = lsum[i] * fac[i] + rs;
#pragma unroll
            for (int j = 0; j < 4; ++j) acc[i][j] *= fac[i];
        }

        __syncthreads();                 // all S-reads of KP done
        // store P into KP as [i][j]
#pragma unroll
        for (int i = 0; i < 4; ++i)
            *(float4*)&KP[4 * ty + i][4 * tx] = *(float4*)&S[i][0];
        __syncthreads();

        // acc += P @ V
        for (int j = 0; j < 64; ++j) {
            float4 vb = *(const float4*)&Vs[j][4 * tx];
#pragma unroll
            for (int i = 0; i < 4; ++i) {
                const float p = KP[4 * ty + i][j];
                acc[i][0] = fmaf(p, vb.x, acc[i][0]);
                acc[i][1] = fmaf(p, vb.y, acc[i][1]);
                acc[i][2] = fmaf(p, vb.z, acc[i][2]);
                acc[i][3] = fmaf(p, vb.w, acc[i][3]);
            }
        }
    }

    // write Y[t, h*64 + d]
#pragma unroll
    for (int i = 0; i < 4; ++i) {
        const float inv = 1.f / lsum[i];
        float4 o = make_float4(acc[i][0] * inv, acc[i][1] * inv,
                               acc[i][2] * inv, acc[i][3] * inv);
        *(float4*)&Y[(size_t)(m0 + 4 * ty + i) * CDIM + h * 64 + 4 * tx] = o;
    }
}

// ---------------------------------------------------------------------------
extern "C" void kernel_launch(void* const* d_in, const int* in_sizes, int n_in,
                              void* d_out, int out_size)
{
    const float* x      = (const float*)d_in[0];
    const float* cosb   = (const float*)d_in[1];
    const float* sinb   = (const float*)d_in[2];
    const float* W_attn = (const float*)d_in[3];
    const float* b_attn = (const float*)d_in[4];
    const float* W_proj = (const float*)d_in[5];
    const float* b_proj = (const float*)d_in[6];
    float* out = (float*)d_out;

    float* qkv_s = nullptr;
    float* y_s   = nullptr;
    cudaGetSymbolAddress((void**)&qkv_s, g_qkv);
    cudaGetSymbolAddress((void**)&y_s,   g_y);

    // 1) QKV GEMM + bias
    gemm_nt_bias<TSEQ, QKVD, CDIM>
        <<<dim3(QKVD / 128, TSEQ / 128), 256>>>(x, W_attn, b_attn, qkv_s);

    // 2) RoPE in-place
    rope_kernel<<<(TSEQ * 40 * 8 + 255) / 256, 256>>>(qkv_s, cosb, sinb);

    // 3) causal flash attention
    flash_kernel<<<dim3(TSEQ / 64, NHEAD), 256>>>(qkv_s, y_s);

    // 4) output projection + bias
    gemm_nt_bias<TSEQ, CDIM, CDIM>
        <<<dim3(CDIM / 128, TSEQ / 128), 256>>>(y_s, W_proj, b_proj, out);
}

// round 4
// speedup vs baseline: 1.5863x; 1.5863x over previous
#include <cuda_runtime.h>
#include <cuda_bf16.h>
#include <math.h>
#include <stdint.h>

#define TSEQ 2048
#define CDIM 2048
#define QKVD 3072
#define NHEAD 32
#define HSZ 64

// scratch (no allocations allowed)
__device__ float g_qkv[TSEQ * QKVD];   // 24 MB
__device__ float g_y[TSEQ * CDIM];     // 16 MB

// ---------------------------------------------------------------------------
// helpers
// ---------------------------------------------------------------------------
__device__ __forceinline__ uint32_t smem_u32(const void* p) {
    uint32_t a;
    asm("{ .reg .u64 t; cvta.to.shared.u64 t, %1; cvt.u32.u64 %0, t; }"
        : "=r"(a) : "l"(p));
    return a;
}

__device__ __forceinline__ void ldmatrix_x4(uint32_t& r0, uint32_t& r1,
                                            uint32_t& r2, uint32_t& r3,
                                            uint32_t addr) {
    asm volatile("ldmatrix.sync.aligned.m8n8.x4.shared.b16 {%0,%1,%2,%3}, [%4];"
                 : "=r"(r0), "=r"(r1), "=r"(r2), "=r"(r3) : "r"(addr));
}

__device__ __forceinline__ void mma16816(float* c, const uint32_t* a,
                                         uint32_t b0, uint32_t b1) {
    asm volatile(
        "mma.sync.aligned.m16n8k16.row.col.f32.bf16.bf16.f32 "
        "{%0,%1,%2,%3}, {%4,%5,%6,%7}, {%8,%9}, {%0,%1,%2,%3};"
        : "+f"(c[0]), "+f"(c[1]), "+f"(c[2]), "+f"(c[3])
        : "r"(a[0]), "r"(a[1]), "r"(a[2]), "r"(a[3]), "r"(b0), "r"(b1));
}

#define SWZ(o) ((o) ^ (((o) >> 3) & 0x70))

// fp32 float4 -> bf16 hi (8B) + bf16 lo (8B) swizzled stores
__device__ __forceinline__ void cvt_split_store(uint32_t hi_addr, uint32_t lo_addr,
                                                float4 v) {
    __nv_bfloat162 h01 = __floats2bfloat162_rn(v.x, v.y);
    __nv_bfloat162 h23 = __floats2bfloat162_rn(v.z, v.w);
    float2 f01 = __bfloat1622float2(h01);
    float2 f23 = __bfloat1622float2(h23);
    __nv_bfloat162 l01 = __floats2bfloat162_rn(v.x - f01.x, v.y - f01.y);
    __nv_bfloat162 l23 = __floats2bfloat162_rn(v.z - f23.x, v.w - f23.y);
    uint32_t uh0 = *reinterpret_cast<uint32_t*>(&h01);
    uint32_t uh1 = *reinterpret_cast<uint32_t*>(&h23);
    uint32_t ul0 = *reinterpret_cast<uint32_t*>(&l01);
    uint32_t ul1 = *reinterpret_cast<uint32_t*>(&l23);
    asm volatile("st.shared.v2.b32 [%0], {%1, %2};" :: "r"(hi_addr), "r"(uh0), "r"(uh1) : "memory");
    asm volatile("st.shared.v2.b32 [%0], {%1, %2};" :: "r"(lo_addr), "r"(ul0), "r"(ul1) : "memory");
}

// ---------------------------------------------------------------------------
// mma.sync bf16x3 NT GEMM: C[M,N] = A[M,K] * B[N,K]^T + bias[N]
// 128x128 CTA tile, BK=64, 256 threads (8 warps, 2x4), warp tile 64x32.
// Double-buffered smem: per stage Ahi(16K) Alo(16K) Bhi(16K) Blo(16K).
// ---------------------------------------------------------------------------
static constexpr int GSTAGE = 65536;
static constexpr int GEMM_SMEM_BYTES = 1024 + 2 * GSTAGE;

template<int NDIM, int KDIM>
__global__ void __launch_bounds__(256, 1)
gemm_mma(const float* __restrict__ A, const float* __restrict__ B,
         const float* __restrict__ bias, float* __restrict__ C)
{
    extern __shared__ char smem_raw[];
    const uint32_t sb = (smem_u32(smem_raw) + 1023u) & ~1023u;

    const int tid  = threadIdx.x;
    const int wid  = tid >> 5;
    const int lane = tid & 31;
    const int m0 = blockIdx.y * 128;
    const int n0 = blockIdx.x * 128;

    const int wm = (wid >> 2) * 64;    // warp m-offset in tile
    const int wn = (wid & 3) * 32;     // warp n-offset in tile

    // staging indices (shared by all warps)
    const int srow = tid >> 1;              // not used; keep conversion mapping below
    (void)srow;

    const float* Abase = A + (size_t)m0 * KDIM;
    const float* Bbase = B + (size_t)n0 * KDIM;

    float acc[4][4][4];
#pragma unroll
    for (int i = 0; i < 4; ++i)
#pragma unroll
        for (int j = 0; j < 4; ++j)
#pragma unroll
            for (int r = 0; r < 4; ++r) acc[i][j][r] = 0.f;

    // ldmatrix per-lane row/col-half within a 16x16 bf16 tile
    const int lrow16 = lane & 15;           // row within 16
    const int khalfB = (lane >> 4) * 16;    // byte offset of k-half

    const int ITERS = KDIM / 64;
    float4 pa[8], pb[8];

    // prologue: load kt=0
#pragma unroll
    for (int c = 0; c < 8; ++c) {
        const int idx = c * 256 + tid;
        const int row = idx >> 4;
        const int f4  = idx & 15;
        pa[c] = *(const float4*)(Abase + (size_t)row * KDIM + f4 * 4);
        pb[c] = *(const float4*)(Bbase + (size_t)row * KDIM + f4 * 4);
    }
    {
        const uint32_t stg = sb + 1024;
#pragma unroll
        for (int c = 0; c < 8; ++c) {
            const int idx = c * 256 + tid;
            const int row = idx >> 4;
            const int f4  = idx & 15;
            const uint32_t off = SWZ((uint32_t)(row * 128 + f4 * 8));
            cvt_split_store(stg + off,         stg + 16384 + off, pa[c]);
            cvt_split_store(stg + 32768 + off, stg + 49152 + off, pb[c]);
        }
    }
    __syncthreads();

    for (int kt = 0; kt < ITERS; ++kt) {
        const uint32_t stg = sb + 1024 + (kt & 1) * GSTAGE;
        const bool more = (kt + 1 < ITERS);

        // prefetch next K-block to registers (overlaps with MMAs below)
        if (more) {
            const float* Ag = Abase + (kt + 1) * 64;
            const float* Bg = Bbase + (kt + 1) * 64;
#pragma unroll
            for (int c = 0; c < 8; ++c) {
                const int idx = c * 256 + tid;
                const int row = idx >> 4;
                const int f4  = idx & 15;
                pa[c] = *(const float4*)(Ag + (size_t)row * KDIM + f4 * 4);
                pb[c] = *(const float4*)(Bg + (size_t)row * KDIM + f4 * 4);
            }
        }

        // compute this K-block: 4 k16 steps
#pragma unroll
        for (int s = 0; s < 4; ++s) {
            const uint32_t kb = (uint32_t)(s * 32 + khalfB);
            // B fragments (hi & lo), 2 x ldmatrix.x4 each covering 16 n-rows
            uint32_t bh[2][4], bl[2][4];
#pragma unroll
            for (int nj2 = 0; nj2 < 2; ++nj2) {
                const uint32_t roff = SWZ((uint32_t)((wn + nj2 * 16 + lrow16) * 128) + kb);
                ldmatrix_x4(bh[nj2][0], bh[nj2][1], bh[nj2][2], bh[nj2][3],
                            stg + 32768 + roff);
                ldmatrix_x4(bl[nj2][0], bl[nj2][1], bl[nj2][2], bl[nj2][3],
                            stg + 49152 + roff);
            }
#pragma unroll
            for (int mi = 0; mi < 4; ++mi) {
                const uint32_t aoff = SWZ((uint32_t)((wm + mi * 16 + lrow16) * 128) + kb);
                uint32_t ah[4], al[4];
                ldmatrix_x4(ah[0], ah[1], ah[2], ah[3], stg + aoff);
                ldmatrix_x4(al[0], al[1], al[2], al[3], stg + 16384 + aoff);
#pragma unroll
                for (int nj = 0; nj < 4; ++nj) {
                    const int nj2 = nj >> 1;
                    const int sel = nj & 1;
                    const uint32_t b0h = bh[nj2][sel], b1h = bh[nj2][sel + 2];
                    const uint32_t b0l = bl[nj2][sel], b1l = bl[nj2][sel + 2];
                    mma16816(acc[mi][nj], ah, b0h, b1h);   // hi*hi
                    mma16816(acc[mi][nj], ah, b0l, b1l);   // hi*lo
                    mma16816(acc[mi][nj], al, b0h, b1h);   // lo*hi
                }
            }
        }

        // store prefetched block into the other stage
        if (more) {
            const uint32_t stg2 = sb + 1024 + ((kt + 1) & 1) * GSTAGE;
#pragma unroll
            for (int c = 0; c < 8; ++c) {
                const int idx = c * 256 + tid;
                const int row = idx >> 4;
                const int f4  = idx & 15;
                const uint32_t off = SWZ((uint32_t)(row * 128 + f4 * 8));
                cvt_split_store(stg2 + off,         stg2 + 16384 + off, pa[c]);
                cvt_split_store(stg2 + 32768 + off, stg2 + 49152 + off, pb[c]);
            }
        }
        __syncthreads();
    }

    // epilogue: acc -> C + bias
    const int qrow = lane >> 2;          // 0..7
    const int qcol = (lane & 3) * 2;     // 0,2,4,6
#pragma unroll
    for (int mi = 0; mi < 4; ++mi) {
        const int r0 = m0 + wm + mi * 16 + qrow;
#pragma unroll
        for (int nj = 0; nj < 4; ++nj) {
            const int c0 = n0 + wn + nj * 8 + qcol;
            const float bx = bias[c0], by = bias[c0 + 1];
            float2 o0 = make_float2(acc[mi][nj][0] + bx, acc[mi][nj][1] + by);
            float2 o1 = make_float2(acc[mi][nj][2] + bx, acc[mi][nj][3] + by);
            *(float2*)&C[(size_t)r0 * NDIM + c0]       = o0;
            *(float2*)&C[(size_t)(r0 + 8) * NDIM + c0] = o1;
        }
    }
}

// ---------------------------------------------------------------------------
// RoPE in-place on qkv[T, 3072]. 40 rope-heads per token (32 q + 8 k).
// ---------------------------------------------------------------------------
__global__ void rope_kernel(float* __restrict__ qkv,
                            const float* __restrict__ cosb,
                            const float* __restrict__ sinb)
{
    const int idx = blockIdx.x * 256 + threadIdx.x;   // [0, TSEQ*320)
    if (idx >= TSEQ * 40 * 8) return;
    const int d  = idx & 7;
    const int r  = (idx >> 3) % 40;
    const int t  = idx / 320;
    int gg, ss;
    if (r < 32) { gg = r >> 2; ss = r & 3; }
    else        { gg = r - 32; ss = 4; }
    const int base = t * QKVD + gg * 384 + ss * 64;
    const float x1 = qkv[base + d];
    const float x2 = qkv[base + d + 8];
    const float c1 = cosb[t * 16 + d],     s1 = sinb[t * 16 + d];
    const float c2 = cosb[t * 16 + d + 8], s2 = sinb[t * 16 + d + 8];
    qkv[base + d]     = x1 * c1 - x2 * s1;
    qkv[base + d + 8] = x2 * c2 + x1 * s2;
}

// ---------------------------------------------------------------------------
// Flash attention, causal, fp32. 64x64 tiles, 256 threads (16x16), 4x4 micro.
// ---------------------------------------------------------------------------
__global__ void __launch_bounds__(256, 2) flash_kernel(
    const float* __restrict__ qkv, float* __restrict__ Y)
{
    __shared__ float Qts[64][64];   // [d][i]
    __shared__ float KP[64][64];    // Kt [d][j], then P [i][j]
    __shared__ float Vs[64][64];    // [j][d]

    const int h  = blockIdx.y;
    const int m0 = ((int)gridDim.x - 1 - (int)blockIdx.x) * 64;  // heavy tiles first
    const int gg = h >> 2;
    const int qoff = gg * 384 + (h & 3) * 64;
    const int koff = gg * 384 + 256;
    const int voff = gg * 384 + 320;

    const int tid = threadIdx.x;
    const int tx  = tid & 15;
    const int ty  = tid >> 4;
    const int lrow = tid >> 2;         // 0..63
    const int ld0  = (tid & 3) * 16;   // 0,16,32,48

    {
        const float* qp = qkv + (size_t)(m0 + lrow) * QKVD + qoff + ld0;
#pragma unroll
        for (int c = 0; c < 4; ++c) {
            float4 v = *(const float4*)(qp + 4 * c);
            Qts[ld0 + 4 * c + 0][lrow] = v.x;
            Qts[ld0 + 4 * c + 1][lrow] = v.y;
            Qts[ld0 + 4 * c + 2][lrow] = v.z;
            Qts[ld0 + 4 * c + 3][lrow] = v.w;
        }
    }

    float mrow[4], lsum[4], acc[4][4];
#pragma unroll
    for (int i = 0; i < 4; ++i) {
        mrow[i] = -1e30f; lsum[i] = 0.f;
#pragma unroll
        for (int j = 0; j < 4; ++j) acc[i][j] = 0.f;
    }

    const float scale = 0.125f;   // 1/sqrt(64)

    for (int n0 = 0; n0 <= m0; n0 += 64) {
        __syncthreads();
        {
            const float* kp = qkv + (size_t)(n0 + lrow) * QKVD + koff + ld0;
            const float* vp = qkv + (size_t)(n0 + lrow) * QKVD + voff + ld0;
#pragma unroll
            for (int c = 0; c < 4; ++c) {
                float4 kv = *(const float4*)(kp + 4 * c);
                KP[ld0 + 4 * c + 0][lrow] = kv.x;
                KP[ld0 + 4 * c + 1][lrow] = kv.y;
                KP[ld0 + 4 * c + 2][lrow] = kv.z;
                KP[ld0 + 4 * c + 3][lrow] = kv.w;
                float4 vv = *(const float4*)(vp + 4 * c);
                *(float4*)&Vs[lrow][ld0 + 4 * c] = vv;
            }
        }
        __syncthreads();

        float S[4][4];
#pragma unroll
        for (int i = 0; i < 4; ++i)
#pragma unroll
            for (int j = 0; j < 4; ++j) S[i][j] = 0.f;

        for (int d = 0; d < 64; ++d) {
            float4 qa = *(const float4*)&Qts[d][4 * ty];
            float4 kb = *(const float4*)&KP[d][4 * tx];
            float a[4] = {qa.x, qa.y, qa.z, qa.w};
            float b[4] = {kb.x, kb.y, kb.z, kb.w};
#pragma unroll
            for (int i = 0; i < 4; ++i)
#pragma unroll
                for (int j = 0; j < 4; ++j)
                    S[i][j] = fmaf(a[i], b[j], S[i][j]);
        }

        const bool diag = (n0 == m0);
#pragma unroll
        for (int i = 0; i < 4; ++i)
#pragma unroll
            for (int j = 0; j < 4; ++j) {
                S[i][j] *= scale;
                if (diag && (4 * tx + j) > (4 * ty + i)) S[i][j] = -1e30f;
            }

        float fac[4];
#pragma unroll
        for (int i = 0; i < 4; ++i) {
            float mx = fmaxf(fmaxf(S[i][0], S[i][1]), fmaxf(S[i][2], S[i][3]));
#pragma unroll
            for (int w = 1; w < 16; w <<= 1)
                mx = fmaxf(mx, __shfl_xor_sync(0xffffffffu, mx, w));
            const float mnew = fmaxf(mrow[i], mx);
            fac[i]  = __expf(mrow[i] - mnew);
            mrow[i] = mnew;
            float rs = 0.f;
#pragma unroll
            for (int j = 0; j < 4; ++j) {
                S[i][j] = __expf(S[i][j] - mnew);
                rs += S[i][j];
            }
#pragma unroll
            for (int w = 1; w < 16; w <<= 1)
                rs += __shfl_xor_sync(0xffffffffu, rs, w);
            lsum[i] = lsum[i] * fac[i] + rs;
#pragma unroll
            for (int j = 0; j < 4; ++j) acc[i][j] *= fac[i];
        }

        __syncthreads();
#pragma unroll
        for (int i = 0; i < 4; ++i)
            *(float4*)&KP[4 * ty + i][4 * tx] = *(float4*)&S[i][0];
        __syncthreads();

        for (int j = 0; j < 64; ++j) {
            float4 vb = *(const float4*)&Vs[j][4 * tx];
#pragma unroll
            for (int i = 0; i < 4; ++i) {
                const float p = KP[4 * ty + i][j];
                acc[i][0] = fmaf(p, vb.x, acc[i][0]);
                acc[i][1] = fmaf(p, vb.y, acc[i][1]);
                acc[i][2] = fmaf(p, vb.z, acc[i][2]);
                acc[i][3] = fmaf(p, vb.w, acc[i][3]);
            }
        }
    }

#pragma unroll
    for (int i = 0; i < 4; ++i) {
        const float inv = 1.f / lsum[i];
        float4 o = make_float4(acc[i][0] * inv, acc[i][1] * inv,
                               acc[i][2] * inv, acc[i][3] * inv);
        *(float4*)&Y[(size_t)(m0 + 4 * ty + i) * CDIM + h * 64 + 4 * tx] = o;
    }
}

// ---------------------------------------------------------------------------
extern "C" void kernel_launch(void* const* d_in, const int* in_sizes, int n_in,
                              void* d_out, int out_size)
{
    const float* x      = (const float*)d_in[0];
    const float* cosb   = (const float*)d_in[1];
    const float* sinb   = (const float*)d_in[2];
    const float* W_attn = (const float*)d_in[3];
    const float* b_attn = (const float*)d_in[4];
    const float* W_proj = (const float*)d_in[5];
    const float* b_proj = (const float*)d_in[6];
    float* out = (float*)d_out;

    float* qkv_s = nullptr;
    float* y_s   = nullptr;
    cudaGetSymbolAddress((void**)&qkv_s, g_qkv);
    cudaGetSymbolAddress((void**)&y_s,   g_y);

    cudaFuncSetAttribute(gemm_mma<QKVD, CDIM>,
                         cudaFuncAttributeMaxDynamicSharedMemorySize, GEMM_SMEM_BYTES);
    cudaFuncSetAttribute(gemm_mma<CDIM, CDIM>,
                         cudaFuncAttributeMaxDynamicSharedMemorySize, GEMM_SMEM_BYTES);

    // 1) QKV GEMM + bias (mma.sync bf16x3)
    gemm_mma<QKVD, CDIM>
        <<<dim3(QKVD / 128, TSEQ / 128), 256, GEMM_SMEM_BYTES>>>(x, W_attn, b_attn, qkv_s);

    // 2) RoPE in-place
    rope_kernel<<<(TSEQ * 40 * 8 + 255) / 256, 256>>>(qkv_s, cosb, sinb);

    // 3) causal flash attention (fp32 — next optimization target)
    flash_kernel<<<dim3(TSEQ / 64, NHEAD), 256>>>(qkv_s, y_s);

    // 4) output projection + bias (mma.sync bf16x3)
    gemm_mma<CDIM, CDIM>
        <<<dim3(CDIM / 128, TSEQ / 128), 256, GEMM_SMEM_BYTES>>>(y_s, W_proj, b_proj, out);
}

// round 6
// speedup vs baseline: 2.9032x; 1.8301x over previous
#include <cuda_runtime.h>
#include <cuda_bf16.h>
#include <math.h>
#include <stdint.h>

#define TSEQ 2048
#define CDIM 2048
#define QKVD 3072
#define NHEAD 32
#define HSZ 64

// scratch (no allocations allowed)
__device__ float g_qkv[TSEQ * QKVD];            // 24 MB fp32 qkv (GEMM out)
__device__ float g_y[TSEQ * CDIM];              // 16 MB attention out
__device__ __nv_bfloat16 g_qh[TSEQ * QKVD];     // 12 MB bf16 hi
__device__ __nv_bfloat16 g_ql[TSEQ * QKVD];     // 12 MB bf16 lo

// ---------------------------------------------------------------------------
// helpers
// ---------------------------------------------------------------------------
__device__ __forceinline__ uint32_t smem_u32(const void* p) {
    uint32_t a;
    asm("{ .reg .u64 t; cvta.to.shared.u64 t, %1; cvt.u32.u64 %0, t; }"
        : "=r"(a) : "l"(p));
    return a;
}

__device__ __forceinline__ void ldmatrix_x4(uint32_t& r0, uint32_t& r1,
                                            uint32_t& r2, uint32_t& r3,
                                            uint32_t addr) {
    asm volatile("ldmatrix.sync.aligned.m8n8.x4.shared.b16 {%0,%1,%2,%3}, [%4];"
                 : "=r"(r0), "=r"(r1), "=r"(r2), "=r"(r3) : "r"(addr));
}

__device__ __forceinline__ void ldmatrix_x4_t(uint32_t& r0, uint32_t& r1,
                                              uint32_t& r2, uint32_t& r3,
                                              uint32_t addr) {
    asm volatile("ldmatrix.sync.aligned.m8n8.x4.trans.shared.b16 {%0,%1,%2,%3}, [%4];"
                 : "=r"(r0), "=r"(r1), "=r"(r2), "=r"(r3) : "r"(addr));
}

__device__ __forceinline__ void mma16816(float* c, const uint32_t* a,
                                         uint32_t b0, uint32_t b1) {
    asm volatile(
        "mma.sync.aligned.m16n8k16.row.col.f32.bf16.bf16.f32 "
        "{%0,%1,%2,%3}, {%4,%5,%6,%7}, {%8,%9}, {%0,%1,%2,%3};"
        : "+f"(c[0]), "+f"(c[1]), "+f"(c[2]), "+f"(c[3])
        : "r"(a[0]), "r"(a[1]), "r"(a[2]), "r"(a[3]), "r"(b0), "r"(b1));
}

__device__ __forceinline__ void cp16(uint32_t dst, const void* src) {
    asm volatile("cp.async.cg.shared.global [%0], [%1], 16;"
                 :: "r"(dst), "l"(src) : "memory");
}
__device__ __forceinline__ void cp_commit() {
    asm volatile("cp.async.commit_group;" ::: "memory");
}
template<int N> __device__ __forceinline__ void cp_wait() {
    asm volatile("cp.async.wait_group %0;" :: "n"(N) : "memory");
}

#define SWZ(o) ((o) ^ (((o) >> 3) & 0x70))

// fp32 pair -> packed bf16 hi + bf16 lo (residual)
__device__ __forceinline__ void pack_hl(float x, float y, uint32_t& h, uint32_t& l) {
    __nv_bfloat162 hh = __floats2bfloat162_rn(x, y);
    float2 f = __bfloat1622float2(hh);
    __nv_bfloat162 ll = __floats2bfloat162_rn(x - f.x, y - f.y);
    h = *reinterpret_cast<uint32_t*>(&hh);
    l = *reinterpret_cast<uint32_t*>(&ll);
}

// fp32 float4 -> bf16 hi (8B) + bf16 lo (8B) swizzled stores
__device__ __forceinline__ void cvt_split_store(uint32_t hi_addr, uint32_t lo_addr,
                                                float4 v) {
    uint32_t uh0, ul0, uh1, ul1;
    pack_hl(v.x, v.y, uh0, ul0);
    pack_hl(v.z, v.w, uh1, ul1);
    asm volatile("st.shared.v2.b32 [%0], {%1, %2};" :: "r"(hi_addr), "r"(uh0), "r"(uh1) : "memory");
    asm volatile("st.shared.v2.b32 [%0], {%1, %2};" :: "r"(lo_addr), "r"(ul0), "r"(ul1) : "memory");
}

// ---------------------------------------------------------------------------
// mma.sync bf16x3 NT GEMM: C[M,N] = A[M,K] * B[N,K]^T + bias[N]
// (unchanged from round 4 — 187us for 2048^3)
// ---------------------------------------------------------------------------
static constexpr int GSTAGE = 65536;
static constexpr int GEMM_SMEM_BYTES = 1024 + 2 * GSTAGE;

template<int NDIM, int KDIM>
__global__ void __launch_bounds__(256, 1)
gemm_mma(const float* __restrict__ A, const float* __restrict__ B,
         const float* __restrict__ bias, float* __restrict__ C)
{
    extern __shared__ char smem_raw[];
    const uint32_t sb = (smem_u32(smem_raw) + 1023u) & ~1023u;

    const int tid  = threadIdx.x;
    const int wid  = tid >> 5;
    const int lane = tid & 31;
    const int m0 = blockIdx.y * 128;
    const int n0 = blockIdx.x * 128;

    const int wm = (wid >> 2) * 64;
    const int wn = (wid & 3) * 32;

    const float* Abase = A + (size_t)m0 * KDIM;
    const float* Bbase = B + (size_t)n0 * KDIM;

    float acc[4][4][4];
#pragma unroll
    for (int i = 0; i < 4; ++i)
#pragma unroll
        for (int j = 0; j < 4; ++j)
#pragma unroll
            for (int r = 0; r < 4; ++r) acc[i][j][r] = 0.f;

    const int lrow16 = lane & 15;
    const int khalfB = (lane >> 4) * 16;

    const int ITERS = KDIM / 64;
    float4 pa[8], pb[8];

#pragma unroll
    for (int c = 0; c < 8; ++c) {
        const int idx = c * 256 + tid;
        const int row = idx >> 4;
        const int f4  = idx & 15;
        pa[c] = *(const float4*)(Abase + (size_t)row * KDIM + f4 * 4);
        pb[c] = *(const float4*)(Bbase + (size_t)row * KDIM + f4 * 4);
    }
    {
        const uint32_t stg = sb + 1024;
#pragma unroll
        for (int c = 0; c < 8; ++c) {
            const int idx = c * 256 + tid;
            const int row = idx >> 4;
            const int f4  = idx & 15;
            const uint32_t off = SWZ((uint32_t)(row * 128 + f4 * 8));
            cvt_split_store(stg + off,         stg + 16384 + off, pa[c]);
            cvt_split_store(stg + 32768 + off, stg + 49152 + off, pb[c]);
        }
    }
    __syncthreads();

    for (int kt = 0; kt < ITERS; ++kt) {
        const uint32_t stg = sb + 1024 + (kt & 1) * GSTAGE;
        const bool more = (kt + 1 < ITERS);

        if (more) {
            const float* Ag = Abase + (kt + 1) * 64;
            const float* Bg = Bbase + (kt + 1) * 64;
#pragma unroll
            for (int c = 0; c < 8; ++c) {
                const int idx = c * 256 + tid;
                const int row = idx >> 4;
                const int f4  = idx & 15;
                pa[c] = *(const float4*)(Ag + (size_t)row * KDIM + f4 * 4);
                pb[c] = *(const float4*)(Bg + (size_t)row * KDIM + f4 * 4);
            }
        }

#pragma unroll
        for (int s = 0; s < 4; ++s) {
            const uint32_t kb = (uint32_t)(s * 32 + khalfB);
            uint32_t bh[2][4], bl[2][4];
#pragma unroll
            for (int nj2 = 0; nj2 < 2; ++nj2) {
                const uint32_t roff = SWZ((uint32_t)((wn + nj2 * 16 + lrow16) * 128) + kb);
                ldmatrix_x4(bh[nj2][0], bh[nj2][1], bh[nj2][2], bh[nj2][3],
                            stg + 32768 + roff);
                ldmatrix_x4(bl[nj2][0], bl[nj2][1], bl[nj2][2], bl[nj2][3],
                            stg + 49152 + roff);
            }
#pragma unroll
            for (int mi = 0; mi < 4; ++mi) {
                const uint32_t aoff = SWZ((uint32_t)((wm + mi * 16 + lrow16) * 128) + kb);
                uint32_t ah[4], al[4];
                ldmatrix_x4(ah[0], ah[1], ah[2], ah[3], stg + aoff);
                ldmatrix_x4(al[0], al[1], al[2], al[3], stg + 16384 + aoff);
#pragma unroll
                for (int nj = 0; nj < 4; ++nj) {
                    const int nj2 = nj >> 1;
                    const int sel = nj & 1;
                    const uint32_t b0h = bh[nj2][sel], b1h = bh[nj2][sel + 2];
                    const uint32_t b0l = bl[nj2][sel], b1l = bl[nj2][sel + 2];
                    mma16816(acc[mi][nj], ah, b0h, b1h);
                    mma16816(acc[mi][nj], ah, b0l, b1l);
                    mma16816(acc[mi][nj], al, b0h, b1h);
                }
            }
        }

        if (more) {
            const uint32_t stg2 = sb + 1024 + ((kt + 1) & 1) * GSTAGE;
#pragma unroll
            for (int c = 0; c < 8; ++c) {
                const int idx = c * 256 + tid;
                const int row = idx >> 4;
                const int f4  = idx & 15;
                const uint32_t off = SWZ((uint32_t)(row * 128 + f4 * 8));
                cvt_split_store(stg2 + off,         stg2 + 16384 + off, pa[c]);
                cvt_split_store(stg2 + 32768 + off, stg2 + 49152 + off, pb[c]);
            }
        }
        __syncthreads();
    }

    const int qrow = lane >> 2;
    const int qcol = (lane & 3) * 2;
#pragma unroll
    for (int mi = 0; mi < 4; ++mi) {
        const int r0 = m0 + wm + mi * 16 + qrow;
#pragma unroll
        for (int nj = 0; nj < 4; ++nj) {
            const int c0 = n0 + wn + nj * 8 + qcol;
            const float bx = bias[c0], by = bias[c0 + 1];
            float2 o0 = make_float2(acc[mi][nj][0] + bx, acc[mi][nj][1] + by);
            float2 o1 = make_float2(acc[mi][nj][2] + bx, acc[mi][nj][3] + by);
            *(float2*)&C[(size_t)r0 * NDIM + c0]       = o0;
            *(float2*)&C[(size_t)(r0 + 8) * NDIM + c0] = o1;
        }
    }
}

// ---------------------------------------------------------------------------
// RoPE + bf16 hi/lo convert. One warp per (token, slot-of-64).
// Slot layout per group g of 6: [q0 q1 q2 q3 k v]. RoPE on q,k dims [0,16).
// Q additionally scaled by 1/sqrt(64) (folded softmax scale).
// ---------------------------------------------------------------------------
__global__ void __launch_bounds__(256)
rope_convert(const float* __restrict__ qkv,
             const float* __restrict__ cosb, const float* __restrict__ sinb,
             __nv_bfloat16* __restrict__ qh, __nv_bfloat16* __restrict__ ql)
{
    const int gid  = blockIdx.x * 8 + (threadIdx.x >> 5);
    const int lane = threadIdx.x & 31;
    const int t = gid / 48;
    const int s = gid % 48;
    const int ss = s % 6;                 // 0-3 q, 4 k, 5 v
    const int d = 2 * lane;

    const size_t off = (size_t)t * QKVD + s * 64 + d;
    float2 v = *(const float2*)(qkv + off);

    // rope partner (d xor 8): lanes 0-7 hold d 0..15; shfl xor 4 swaps halves
    float px = __shfl_xor_sync(0xffffffffu, v.x, 4);
    float py = __shfl_xor_sync(0xffffffffu, v.y, 4);
    if (ss < 5 && d < 16) {
        const float rx = (d < 8) ? -px : px;
        const float ry = (d < 8) ? -py : py;
        const float c0 = cosb[t * 16 + d],     s0 = sinb[t * 16 + d];
        const float c1 = cosb[t * 16 + d + 1], s1 = sinb[t * 16 + d + 1];
        v.x = v.x * c0 + rx * s0;
        v.y = v.y * c1 + ry * s1;
    }
    if (ss < 4) { v.x *= 0.125f; v.y *= 0.125f; }   // softmax scale into Q

    uint32_t h, l;
    pack_hl(v.x, v.y, h, l);
    *(uint32_t*)(qh + off) = h;
    *(uint32_t*)(ql + off) = l;
}

// ---------------------------------------------------------------------------
// Flash attention, causal, mma.sync bf16x3.
// CTA: 128 q-rows x one head. 8 warps x M=16. KV blocks of 128, cp.async
// double-buffered. Q frags resident in registers; P packed from accumulators.
// ---------------------------------------------------------------------------
static constexpr int FL_STAGE = 65536;   // Kh,Kl,Vh,Vl 16KB each
static constexpr int FLASH_SMEM_BYTES = 1024 + 32768 + 2 * FL_STAGE;

__device__ __forceinline__ void flash_issue_kv(
    uint32_t SB, const __nv_bfloat16* qh, const __nv_bfloat16* ql,
    int n0, int koff, int voff, int tid)
{
#pragma unroll
    for (int p = 0; p < 4; ++p) {
        const int idx = p * 256 + tid;
        const int row = idx >> 3, ch = idx & 7;
        const uint32_t off = SWZ((uint32_t)(row * 128 + ch * 16));
        const size_t gk = (size_t)(n0 + row) * QKVD + koff + ch * 8;
        const size_t gv = (size_t)(n0 + row) * QKVD + voff + ch * 8;
        cp16(SB + off,         qh + gk);
        cp16(SB + 16384 + off, ql + gk);
        cp16(SB + 32768 + off, qh + gv);
        cp16(SB + 49152 + off, ql + gv);
    }
}

__global__ void __launch_bounds__(256, 1)
flash_mma(const __nv_bfloat16* __restrict__ qh,
          const __nv_bfloat16* __restrict__ ql,
          float* __restrict__ Y)
{
    extern __shared__ char smem_raw[];
    const uint32_t sb = (smem_u32(smem_raw) + 1023u) & ~1023u;

    const int tid  = threadIdx.x;
    const int wid  = tid >> 5;
    const int lane = tid & 31;
    const int h  = blockIdx.x;
    const int m0 = (15 - (int)blockIdx.y) * 128;   // heavy tiles first
    const int nb = m0 / 128 + 1;
    const int g = h >> 2;
    const int qoff = g * 384 + (h & 3) * 64;
    const int koff = g * 384 + 256;
    const int voff = g * 384 + 320;
    const int wm = wid * 16;

    // issue Q + block0 (group 0)
#pragma unroll
    for (int p = 0; p < 4; ++p) {
        const int idx = p * 256 + tid;
        const int row = idx >> 3, ch = idx & 7;
        const uint32_t off = SWZ((uint32_t)(row * 128 + ch * 16));
        const size_t gq = (size_t)(m0 + row) * QKVD + qoff + ch * 8;
        cp16(sb + off,         qh + gq);
        cp16(sb + 16384 + off, ql + gq);
    }
    flash_issue_kv(sb + 32768, qh, ql, 0, koff, voff, tid);
    cp_commit();
    if (nb > 1) {   // block1 (group 1)
        flash_issue_kv(sb + 32768 + FL_STAGE, qh, ql, 128, koff, voff, tid);
        cp_commit();
        cp_wait<1>();
    } else {
        cp_wait<0>();
    }
    __syncthreads();

    // load Q fragments (resident for whole kernel)
    uint32_t qfh[4][4], qfl[4][4];
#pragma unroll
    for (int s = 0; s < 4; ++s) {
        const uint32_t aoff = SWZ((uint32_t)((wm + (lane & 15)) * 128
                                             + s * 32 + (lane >> 4) * 16));
        ldmatrix_x4(qfh[s][0], qfh[s][1], qfh[s][2], qfh[s][3], sb + aoff);
        ldmatrix_x4(qfl[s][0], qfl[s][1], qfl[s][2], qfl[s][3], sb + 16384 + aoff);
    }

    float O[8][4];
#pragma unroll
    for (int nj = 0; nj < 8; ++nj)
#pragma unroll
        for (int r = 0; r < 4; ++r) O[nj][r] = 0.f;
    float m_0 = -1e30f, m_1 = -1e30f, l_0 = 0.f, l_1 = 0.f;

    for (int kt = 0; kt < nb; ++kt) {
        const uint32_t SB = sb + 32768 + (kt & 1) * FL_STAGE;
        const uint32_t VB = SB + 32768;

        // ---- S = Q K^T (bf16x3) ----
        float S[16][4];
#pragma unroll
        for (int nf = 0; nf < 16; ++nf)
#pragma unroll
            for (int r = 0; r < 4; ++r) S[nf][r] = 0.f;

#pragma unroll
        for (int s = 0; s < 4; ++s) {
            const uint32_t kb = (uint32_t)(s * 32 + (lane >> 4) * 16);
#pragma unroll
            for (int njp = 0; njp < 8; ++njp) {
                const uint32_t roff = SWZ((uint32_t)((njp * 16 + (lane & 15)) * 128) + kb);
                uint32_t kh[4], kl[4];
                ldmatrix_x4(kh[0], kh[1], kh[2], kh[3], SB + roff);
                ldmatrix_x4(kl[0], kl[1], kl[2], kl[3], SB + 16384 + roff);
                mma16816(S[2 * njp],     qfh[s], kh[0], kh[2]);
                mma16816(S[2 * njp],     qfh[s], kl[0], kl[2]);
                mma16816(S[2 * njp],     qfl[s], kh[0], kh[2]);
                mma16816(S[2 * njp + 1], qfh[s], kh[1], kh[3]);
                mma16816(S[2 * njp + 1], qfh[s], kl[1], kl[3]);
                mma16816(S[2 * njp + 1], qfl[s], kh[1], kh[3]);
            }
        }

        // ---- causal mask on diagonal block ----
        if (kt == nb - 1) {
            const int bc = 2 * (lane & 3);
            const int lim0 = wm + (lane >> 2);
            const int lim1 = lim0 + 8;
#pragma unroll
            for (int nf = 0; nf < 16; ++nf) {
                const int c0 = nf * 8 + bc;
                if (c0 > lim0)     S[nf][0] = -1e30f;
                if (c0 + 1 > lim0) S[nf][1] = -1e30f;
                if (c0 > lim1)     S[nf][2] = -1e30f;
                if (c0 + 1 > lim1) S[nf][3] = -1e30f;
            }
        }

        // ---- online softmax (rows lane/4 and lane/4+8) ----
        float mx0 = -1e30f, mx1 = -1e30f;
#pragma unroll
        for (int nf = 0; nf < 16; ++nf) {
            mx0 = fmaxf(mx0, fmaxf(S[nf][0], S[nf][1]));
            mx1 = fmaxf(mx1, fmaxf(S[nf][2], S[nf][3]));
        }
        mx0 = fmaxf(mx0, __shfl_xor_sync(0xffffffffu, mx0, 1));
        mx0 = fmaxf(mx0, __shfl_xor_sync(0xffffffffu, mx0, 2));
        mx1 = fmaxf(mx1, __shfl_xor_sync(0xffffffffu, mx1, 1));
        mx1 = fmaxf(mx1, __shfl_xor_sync(0xffffffffu, mx1, 2));
        const float mn0 = fmaxf(m_0, mx0), mn1 = fmaxf(m_1, mx1);
        const float f0 = __expf(m_0 - mn0), f1 = __expf(m_1 - mn1);
        m_0 = mn0; m_1 = mn1;

        float rs0 = 0.f, rs1 = 0.f;
#pragma unroll
        for (int nf = 0; nf < 16; ++nf) {
            S[nf][0] = __expf(S[nf][0] - mn0);
            S[nf][1] = __expf(S[nf][1] - mn0);
            S[nf][2] = __expf(S[nf][2] - mn1);
            S[nf][3] = __expf(S[nf][3] - mn1);
            rs0 += S[nf][0] + S[nf][1];
            rs1 += S[nf][2] + S[nf][3];
        }
        rs0 += __shfl_xor_sync(0xffffffffu, rs0, 1);
        rs0 += __shfl_xor_sync(0xffffffffu, rs0, 2);
        rs1 += __shfl_xor_sync(0xffffffffu, rs1, 1);
        rs1 += __shfl_xor_sync(0xffffffffu, rs1, 2);
        l_0 = l_0 * f0 + rs0;
        l_1 = l_1 * f1 + rs1;
#pragma unroll
        for (int nj = 0; nj < 8; ++nj) {
            O[nj][0] *= f0; O[nj][1] *= f0;
            O[nj][2] *= f1; O[nj][3] *= f1;
        }

        // ---- O += P V (bf16x3); P packed straight from S frags ----
        const uint32_t kr   = (uint32_t)(((lane & 8) ? 8 : 0) + (lane & 7));
        const uint32_t dsel = (lane & 16) ? 8u : 0u;
#pragma unroll
        for (int t = 0; t < 8; ++t) {
            uint32_t ph[4], pl[4];
            pack_hl(S[2 * t][0],     S[2 * t][1],     ph[0], pl[0]);
            pack_hl(S[2 * t][2],     S[2 * t][3],     ph[1], pl[1]);
            pack_hl(S[2 * t + 1][0], S[2 * t + 1][1], ph[2], pl[2]);
            pack_hl(S[2 * t + 1][2], S[2 * t + 1][3], ph[3], pl[3]);
#pragma unroll
            for (int db = 0; db < 64; db += 16) {
                const uint32_t voff2 = SWZ((uint32_t)((t * 16 + kr) * 128
                                                      + (db + dsel) * 2));
                uint32_t vh[4], vl[4];
                ldmatrix_x4_t(vh[0], vh[1], vh[2], vh[3], VB + voff2);
                ldmatrix_x4_t(vl[0], vl[1], vl[2], vl[3], VB + 16384 + voff2);
                const int oj = db / 8;
                mma16816(O[oj],     ph, vh[0], vh[1]);
                mma16816(O[oj],     ph, vl[0], vl[1]);
                mma16816(O[oj],     pl, vh[0], vh[1]);
                mma16816(O[oj + 1], ph, vh[2], vh[3]);
                mma16816(O[oj + 1], ph, vl[2], vl[3]);
                mma16816(O[oj + 1], pl, vh[2], vh[3]);
            }
        }

        __syncthreads();   // done reading this stage
        if (kt + 1 < nb) {
            if (kt + 2 < nb) {
                flash_issue_kv(sb + 32768 + (kt & 1) * FL_STAGE, qh, ql,
                               (kt + 2) * 128, koff, voff, tid);
                cp_commit();
                cp_wait<1>();
            } else {
                cp_wait<0>();
            }
            __syncthreads();
        }
    }

    // ---- write O / l ----
    const float inv0 = 1.f / l_0, inv1 = 1.f / l_1;
    const int r0 = m0 + wm + (lane >> 2);
    const int col0 = h * 64 + 2 * (lane & 3);
#pragma unroll
    for (int nj = 0; nj < 8; ++nj) {
        const int col = col0 + nj * 8;
        *(float2*)&Y[(size_t)r0 * CDIM + col] =
            make_float2(O[nj][0] * inv0, O[nj][1] * inv0);
        *(float2*)&Y[(size_t)(r0 + 8) * CDIM + col] =
            make_float2(O[nj][2] * inv1, O[nj][3] * inv1);
    }
}

// ---------------------------------------------------------------------------
extern "C" void kernel_launch(void* const* d_in, const int* in_sizes, int n_in,
                              void* d_out, int out_size)
{
    const float* x      = (const float*)d_in[0];
    const float* cosb   = (const float*)d_in[1];
    const float* sinb   = (const float*)d_in[2];
    const float* W_attn = (const float*)d_in[3];
    const float* b_attn = (const float*)d_in[4];
    const float* W_proj = (const float*)d_in[5];
    const float* b_proj = (const float*)d_in[6];
    float* out = (float*)d_out;

    float* qkv_s = nullptr;
    float* y_s   = nullptr;
    __nv_bfloat16* qh_s = nullptr;
    __nv_bfloat16* ql_s = nullptr;
    cudaGetSymbolAddress((void**)&qkv_s, g_qkv);
    cudaGetSymbolAddress((void**)&y_s,   g_y);
    cudaGetSymbolAddress((void**)&qh_s,  g_qh);
    cudaGetSymbolAddress((void**)&ql_s,  g_ql);

    cudaFuncSetAttribute(gemm_mma<QKVD, CDIM>,
                         cudaFuncAttributeMaxDynamicSharedMemorySize, GEMM_SMEM_BYTES);
    cudaFuncSetAttribute(gemm_mma<CDIM, CDIM>,
                         cudaFuncAttributeMaxDynamicSharedMemorySize, GEMM_SMEM_BYTES);
    cudaFuncSetAttribute(flash_mma,
                         cudaFuncAttributeMaxDynamicSharedMemorySize, FLASH_SMEM_BYTES);

    // 1) QKV GEMM + bias
    gemm_mma<QKVD, CDIM>
        <<<dim3(QKVD / 128, TSEQ / 128), 256, GEMM_SMEM_BYTES>>>(x, W_attn, b_attn, qkv_s);

    // 2) RoPE + bf16 hi/lo convert (scale folded into Q)
    rope_convert<<<TSEQ * 48 / 8, 256>>>(qkv_s, cosb, sinb, qh_s, ql_s);

    // 3) causal flash attention (mma.sync bf16x3)
    flash_mma<<<dim3(NHEAD, TSEQ / 128), 256, FLASH_SMEM_BYTES>>>(qh_s, ql_s, y_s);

    // 4) output projection + bias
    gemm_mma<CDIM, CDIM>
        <<<dim3(CDIM / 128, TSEQ / 128), 256, GEMM_SMEM_BYTES>>>(y_s, W_proj, b_proj, out);
}

// round 7
// speedup vs baseline: 3.0383x; 1.0466x over previous
#include <cuda_runtime.h>
#include <cuda_bf16.h>
#include <math.h>
#include <stdint.h>

#define TSEQ 2048
#define CDIM 2048
#define QKVD 3072
#define NHEAD 32
#define HSZ 64

// scratch (no allocations allowed) — all bf16 hi/lo pairs
__device__ __nv_bfloat16 g_qh[TSEQ * QKVD];   // qkv hi
__device__ __nv_bfloat16 g_ql[TSEQ * QKVD];   // qkv lo
__device__ __nv_bfloat16 g_xh[TSEQ * CDIM];   // x hi
__device__ __nv_bfloat16 g_xl[TSEQ * CDIM];   // x lo
__device__ __nv_bfloat16 g_wah[QKVD * CDIM];  // W_attn hi
__device__ __nv_bfloat16 g_wal[QKVD * CDIM];  // W_attn lo
__device__ __nv_bfloat16 g_wph[CDIM * CDIM];  // W_proj hi
__device__ __nv_bfloat16 g_wpl[CDIM * CDIM];  // W_proj lo
__device__ __nv_bfloat16 g_yh[TSEQ * CDIM];   // attn out hi
__device__ __nv_bfloat16 g_yl[TSEQ * CDIM];   // attn out lo

// ---------------------------------------------------------------------------
// helpers
// ---------------------------------------------------------------------------
__device__ __forceinline__ uint32_t smem_u32(const void* p) {
    uint32_t a;
    asm("{ .reg .u64 t; cvta.to.shared.u64 t, %1; cvt.u32.u64 %0, t; }"
        : "=r"(a) : "l"(p));
    return a;
}

__device__ __forceinline__ void ldmatrix_x4(uint32_t& r0, uint32_t& r1,
                                            uint32_t& r2, uint32_t& r3,
                                            uint32_t addr) {
    asm volatile("ldmatrix.sync.aligned.m8n8.x4.shared.b16 {%0,%1,%2,%3}, [%4];"
                 : "=r"(r0), "=r"(r1), "=r"(r2), "=r"(r3) : "r"(addr));
}

__device__ __forceinline__ void ldmatrix_x4_t(uint32_t& r0, uint32_t& r1,
                                              uint32_t& r2, uint32_t& r3,
                                              uint32_t addr) {
    asm volatile("ldmatrix.sync.aligned.m8n8.x4.trans.shared.b16 {%0,%1,%2,%3}, [%4];"
                 : "=r"(r0), "=r"(r1), "=r"(r2), "=r"(r3) : "r"(addr));
}

__device__ __forceinline__ void mma16816(float* c, const uint32_t* a,
                                         uint32_t b0, uint32_t b1) {
    asm volatile(
        "mma.sync.aligned.m16n8k16.row.col.f32.bf16.bf16.f32 "
        "{%0,%1,%2,%3}, {%4,%5,%6,%7}, {%8,%9}, {%0,%1,%2,%3};"
        : "+f"(c[0]), "+f"(c[1]), "+f"(c[2]), "+f"(c[3])
        : "r"(a[0]), "r"(a[1]), "r"(a[2]), "r"(a[3]), "r"(b0), "r"(b1));
}

__device__ __forceinline__ void cp16(uint32_t dst, const void* src) {
    asm volatile("cp.async.cg.shared.global [%0], [%1], 16;"
                 :: "r"(dst), "l"(src) : "memory");
}
__device__ __forceinline__ void cp_commit() {
    asm volatile("cp.async.commit_group;" ::: "memory");
}
template<int N> __device__ __forceinline__ void cp_wait() {
    asm volatile("cp.async.wait_group %0;" :: "n"(N) : "memory");
}

#define SWZ(o) ((o) ^ (((o) >> 3) & 0x70))

// fp32 pair -> packed bf16 hi + bf16 lo (residual)
__device__ __forceinline__ void pack_hl(float x, float y, uint32_t& h, uint32_t& l) {
    __nv_bfloat162 hh = __floats2bfloat162_rn(x, y);
    float2 f = __bfloat1622float2(hh);
    __nv_bfloat162 ll = __floats2bfloat162_rn(x - f.x, y - f.y);
    h = *reinterpret_cast<uint32_t*>(&hh);
    l = *reinterpret_cast<uint32_t*>(&ll);
}

__device__ __forceinline__ float2 unpack_hl(uint32_t h, uint32_t l) {
    __nv_bfloat162 hh = *reinterpret_cast<__nv_bfloat162*>(&h);
    __nv_bfloat162 ll = *reinterpret_cast<__nv_bfloat162*>(&l);
    float2 a = __bfloat1622float2(hh);
    float2 b = __bfloat1622float2(ll);
    return make_float2(a.x + b.x, a.y + b.y);
}

// ---------------------------------------------------------------------------
// fp32 -> bf16 hi/lo split converter
// ---------------------------------------------------------------------------
__global__ void __launch_bounds__(256)
cvt_hl(const float* __restrict__ src, __nv_bfloat16* __restrict__ h,
       __nv_bfloat16* __restrict__ l, int npairs)
{
    const int i = blockIdx.x * 256 + threadIdx.x;
    if (i >= npairs) return;
    float2 v = ((const float2*)src)[i];
    uint32_t hh, ll;
    pack_hl(v.x, v.y, hh, ll);
    ((uint32_t*)h)[i] = hh;
    ((uint32_t*)l)[i] = ll;
}

// ---------------------------------------------------------------------------
// bf16 hi/lo NT GEMM: C[M,N] = A[M,K]*B[N,K]^T + bias[N]   (bf16x3 products)
// 128x128 tile, BK=64, 256 threads (2x4 warps, warp tile 64x32),
// 3-stage cp.async pipeline (64KB/stage).
// OUT_HL: write hi/lo bf16 instead of fp32.
// ---------------------------------------------------------------------------
static constexpr int GSTAGE = 65536;
static constexpr int GEMM_SMEM_BYTES = 1024 + 3 * GSTAGE;   // 197632

__device__ __forceinline__ void gemm_issue(
    uint32_t stg, const __nv_bfloat16* a0, const __nv_bfloat16* a1,
    const __nv_bfloat16* b0, const __nv_bfloat16* b1, int KDIM, int tid)
{
    const __nv_bfloat16* base[4] = {a0, a1, b0, b1};
#pragma unroll
    for (int t4 = 0; t4 < 4; ++t4) {
        const uint32_t tb = stg + t4 * 16384;
        const __nv_bfloat16* src = base[t4];
#pragma unroll
        for (int it = 0; it < 4; ++it) {
            const int idx = it * 256 + tid;
            const int row = idx >> 3, ch = idx & 7;
            cp16(tb + SWZ((uint32_t)(row * 128 + ch * 16)),
                 src + (size_t)row * KDIM + ch * 8);
        }
    }
}

template<int NDIM, int KDIM, bool OUT_HL>
__global__ void __launch_bounds__(256, 1)
gemm_bf16(const __nv_bfloat16* __restrict__ Ah, const __nv_bfloat16* __restrict__ Al,
          const __nv_bfloat16* __restrict__ Bh, const __nv_bfloat16* __restrict__ Bl,
          const float* __restrict__ bias, float* __restrict__ C,
          __nv_bfloat16* __restrict__ Ch, __nv_bfloat16* __restrict__ Cl)
{
    extern __shared__ char smem_raw[];
    const uint32_t sb = (smem_u32(smem_raw) + 1023u) & ~1023u;

    const int tid  = threadIdx.x;
    const int wid  = tid >> 5;
    const int lane = tid & 31;
    const int m0 = blockIdx.y * 128;
    const int n0 = blockIdx.x * 128;
    const int wm = (wid >> 2) * 64;
    const int wn = (wid & 3) * 32;

    const __nv_bfloat16* A0 = Ah + (size_t)m0 * KDIM;
    const __nv_bfloat16* A1 = Al + (size_t)m0 * KDIM;
    const __nv_bfloat16* B0 = Bh + (size_t)n0 * KDIM;
    const __nv_bfloat16* B1 = Bl + (size_t)n0 * KDIM;

    float acc[4][4][4];
#pragma unroll
    for (int i = 0; i < 4; ++i)
#pragma unroll
        for (int j = 0; j < 4; ++j)
#pragma unroll
            for (int r = 0; r < 4; ++r) acc[i][j][r] = 0.f;

    const int lrow16 = lane & 15;
    const int khalfB = (lane >> 4) * 16;
    const int ITERS = KDIM / 64;

    gemm_issue(sb,              A0,      A1,      B0,      B1,      KDIM, tid); cp_commit();
    gemm_issue(sb + GSTAGE,     A0 + 64, A1 + 64, B0 + 64, B1 + 64, KDIM, tid); cp_commit();
    gemm_issue(sb + 2 * GSTAGE, A0 + 128, A1 + 128, B0 + 128, B1 + 128, KDIM, tid); cp_commit();

    for (int kt = 0; kt < ITERS; ++kt) {
        const int sidx = kt % 3;
        const uint32_t stg = sb + sidx * GSTAGE;
        cp_wait<2>();
        __syncthreads();

#pragma unroll
        for (int s = 0; s < 4; ++s) {
            const uint32_t kb = (uint32_t)(s * 32 + khalfB);
            uint32_t bh[2][4], bl[2][4];
#pragma unroll
            for (int nj2 = 0; nj2 < 2; ++nj2) {
                const uint32_t roff = SWZ((uint32_t)((wn + nj2 * 16 + lrow16) * 128) + kb);
                ldmatrix_x4(bh[nj2][0], bh[nj2][1], bh[nj2][2], bh[nj2][3],
                            stg + 32768 + roff);
                ldmatrix_x4(bl[nj2][0], bl[nj2][1], bl[nj2][2], bl[nj2][3],
                            stg + 49152 + roff);
            }
#pragma unroll
            for (int mi = 0; mi < 4; ++mi) {
                const uint32_t aoff = SWZ((uint32_t)((wm + mi * 16 + lrow16) * 128) + kb);
                uint32_t ah[4], al[4];
                ldmatrix_x4(ah[0], ah[1], ah[2], ah[3], stg + aoff);
                ldmatrix_x4(al[0], al[1], al[2], al[3], stg + 16384 + aoff);
#pragma unroll
                for (int nj = 0; nj < 4; ++nj) {
                    const int nj2 = nj >> 1;
                    const int sel = nj & 1;
                    const uint32_t b0h = bh[nj2][sel], b1h = bh[nj2][sel + 2];
                    const uint32_t b0l = bl[nj2][sel], b1l = bl[nj2][sel + 2];
                    mma16816(acc[mi][nj], ah, b0h, b1h);
                    mma16816(acc[mi][nj], ah, b0l, b1l);
                    mma16816(acc[mi][nj], al, b0h, b1h);
                }
            }
        }

        __syncthreads();
        if (kt + 3 < ITERS) {
            const int ko = (kt + 3) * 64;
            gemm_issue(stg, A0 + ko, A1 + ko, B0 + ko, B1 + ko, KDIM, tid);
        }
        cp_commit();
    }

    // epilogue
    const int qrow = lane >> 2;
    const int qcol = (lane & 3) * 2;
#pragma unroll
    for (int mi = 0; mi < 4; ++mi) {
        const int r0 = m0 + wm + mi * 16 + qrow;
#pragma unroll
        for (int nj = 0; nj < 4; ++nj) {
            const int c0 = n0 + wn + nj * 8 + qcol;
            const float bx = bias[c0], by = bias[c0 + 1];
            const float v00 = acc[mi][nj][0] + bx, v01 = acc[mi][nj][1] + by;
            const float v10 = acc[mi][nj][2] + bx, v11 = acc[mi][nj][3] + by;
            if (OUT_HL) {
                uint32_t h, l;
                pack_hl(v00, v01, h, l);
                *(uint32_t*)(Ch + (size_t)r0 * NDIM + c0) = h;
                *(uint32_t*)(Cl + (size_t)r0 * NDIM + c0) = l;
                pack_hl(v10, v11, h, l);
                *(uint32_t*)(Ch + (size_t)(r0 + 8) * NDIM + c0) = h;
                *(uint32_t*)(Cl + (size_t)(r0 + 8) * NDIM + c0) = l;
            } else {
                *(float2*)&C[(size_t)r0 * NDIM + c0]       = make_float2(v00, v01);
                *(float2*)&C[(size_t)(r0 + 8) * NDIM + c0] = make_float2(v10, v11);
            }
        }
    }
}

// ---------------------------------------------------------------------------
// RoPE in-place on qkv hi/lo. One warp per (token, rope-slot).
// 40 slots/token: per group of 6 [q0 q1 q2 q3 k v] -> q0..q3,k (v untouched).
// Q scaled by 1/8 (folded softmax scale).
// ---------------------------------------------------------------------------
__global__ void __launch_bounds__(256)
rope_hl(__nv_bfloat16* __restrict__ qh, __nv_bfloat16* __restrict__ ql,
        const float* __restrict__ cosb, const float* __restrict__ sinb)
{
    const int gid  = blockIdx.x * 8 + (threadIdx.x >> 5);
    const int lane = threadIdx.x & 31;
    const int t   = gid / 40;
    const int s40 = gid % 40;
    const int ss  = s40 % 5;             // 0-3 q, 4 k
    const int slot = (s40 / 5) * 6 + ss;
    const int d = 2 * lane;

    const size_t off = (size_t)t * QKVD + slot * 64 + d;
    uint32_t h = *(const uint32_t*)(qh + off);
    uint32_t l = *(const uint32_t*)(ql + off);
    float2 v = unpack_hl(h, l);

    float px = __shfl_xor_sync(0xffffffffu, v.x, 4);
    float py = __shfl_xor_sync(0xffffffffu, v.y, 4);
    if (d < 16) {
        const float rx = (d < 8) ? -px : px;
        const float ry = (d < 8) ? -py : py;
        const float c0 = cosb[t * 16 + d],     s0 = sinb[t * 16 + d];
        const float c1 = cosb[t * 16 + d + 1], s1 = sinb[t * 16 + d + 1];
        v.x = v.x * c0 + rx * s0;
        v.y = v.y * c1 + ry * s1;
    }
    if (ss < 4) { v.x *= 0.125f; v.y *= 0.125f; }

    pack_hl(v.x, v.y, h, l);
    *(uint32_t*)(qh + off) = h;
    *(uint32_t*)(ql + off) = l;
}

// ---------------------------------------------------------------------------
// Flash attention, causal, mma.sync bf16x3 (as round 5), output bf16 hi/lo.
// ---------------------------------------------------------------------------
static constexpr int FL_STAGE = 65536;
static constexpr int FLASH_SMEM_BYTES = 1024 + 32768 + 2 * FL_STAGE;

__device__ __forceinline__ void flash_issue_kv(
    uint32_t SB, const __nv_bfloat16* qh, const __nv_bfloat16* ql,
    int n0, int koff, int voff, int tid)
{
#pragma unroll
    for (int p = 0; p < 4; ++p) {
        const int idx = p * 256 + tid;
        const int row = idx >> 3, ch = idx & 7;
        const uint32_t off = SWZ((uint32_t)(row * 128 + ch * 16));
        const size_t gk = (size_t)(n0 + row) * QKVD + koff + ch * 8;
        const size_t gv = (size_t)(n0 + row) * QKVD + voff + ch * 8;
        cp16(SB + off,         qh + gk);
        cp16(SB + 16384 + off, ql + gk);
        cp16(SB + 32768 + off, qh + gv);
        cp16(SB + 49152 + off, ql + gv);
    }
}

__global__ void __launch_bounds__(256, 1)
flash_mma(const __nv_bfloat16* __restrict__ qh,
          const __nv_bfloat16* __restrict__ ql,
          __nv_bfloat16* __restrict__ yh, __nv_bfloat16* __restrict__ yl)
{
    extern __shared__ char smem_raw[];
    const uint32_t sb = (smem_u32(smem_raw) + 1023u) & ~1023u;

    const int tid  = threadIdx.x;
    const int wid  = tid >> 5;
    const int lane = tid & 31;
    const int h  = blockIdx.x;
    const int m0 = (15 - (int)blockIdx.y) * 128;
    const int nb = m0 / 128 + 1;
    const int g = h >> 2;
    const int qoff = g * 384 + (h & 3) * 64;
    const int koff = g * 384 + 256;
    const int voff = g * 384 + 320;
    const int wm = wid * 16;

#pragma unroll
    for (int p = 0; p < 4; ++p) {
        const int idx = p * 256 + tid;
        const int row = idx >> 3, ch = idx & 7;
        const uint32_t off = SWZ((uint32_t)(row * 128 + ch * 16));
        const size_t gq = (size_t)(m0 + row) * QKVD + qoff + ch * 8;
        cp16(sb + off,         qh + gq);
        cp16(sb + 16384 + off, ql + gq);
    }
    flash_issue_kv(sb + 32768, qh, ql, 0, koff, voff, tid);
    cp_commit();
    if (nb > 1) {
        flash_issue_kv(sb + 32768 + FL_STAGE, qh, ql, 128, koff, voff, tid);
        cp_commit();
        cp_wait<1>();
    } else {
        cp_wait<0>();
    }
    __syncthreads();

    uint32_t qfh[4][4], qfl[4][4];
#pragma unroll
    for (int s = 0; s < 4; ++s) {
        const uint32_t aoff = SWZ((uint32_t)((wm + (lane & 15)) * 128
                                             + s * 32 + (lane >> 4) * 16));
        ldmatrix_x4(qfh[s][0], qfh[s][1], qfh[s][2], qfh[s][3], sb + aoff);
        ldmatrix_x4(qfl[s][0], qfl[s][1], qfl[s][2], qfl[s][3], sb + 16384 + aoff);
    }

    float O[8][4];
#pragma unroll
    for (int nj = 0; nj < 8; ++nj)
#pragma unroll
        for (int r = 0; r < 4; ++r) O[nj][r] = 0.f;
    float m_0 = -1e30f, m_1 = -1e30f, l_0 = 0.f, l_1 = 0.f;

    for (int kt = 0; kt < nb; ++kt) {
        const uint32_t SB = sb + 32768 + (kt & 1) * FL_STAGE;
        const uint32_t VB = SB + 32768;

        float S[16][4];
#pragma unroll
        for (int nf = 0; nf < 16; ++nf)
#pragma unroll
            for (int r = 0; r < 4; ++r) S[nf][r] = 0.f;

#pragma unroll
        for (int s = 0; s < 4; ++s) {
            const uint32_t kb = (uint32_t)(s * 32 + (lane >> 4) * 16);
#pragma unroll
            for (int njp = 0; njp < 8; ++njp) {
                const uint32_t roff = SWZ((uint32_t)((njp * 16 + (lane & 15)) * 128) + kb);
                uint32_t kh[4], kl[4];
                ldmatrix_x4(kh[0], kh[1], kh[2], kh[3], SB + roff);
                ldmatrix_x4(kl[0], kl[1], kl[2], kl[3], SB + 16384 + roff);
                mma16816(S[2 * njp],     qfh[s], kh[0], kh[2]);
                mma16816(S[2 * njp],     qfh[s], kl[0], kl[2]);
                mma16816(S[2 * njp],     qfl[s], kh[0], kh[2]);
                mma16816(S[2 * njp + 1], qfh[s], kh[1], kh[3]);
                mma16816(S[2 * njp + 1], qfh[s], kl[1], kl[3]);
                mma16816(S[2 * njp + 1], qfl[s], kh[1], kh[3]);
            }
        }

        if (kt == nb - 1) {
            const int bc = 2 * (lane & 3);
            const int lim0 = wm + (lane >> 2);
            const int lim1 = lim0 + 8;
#pragma unroll
            for (int nf = 0; nf < 16; ++nf) {
                const int c0 = nf * 8 + bc;
                if (c0 > lim0)     S[nf][0] = -1e30f;
                if (c0 + 1 > lim0) S[nf][1] = -1e30f;
                if (c0 > lim1)     S[nf][2] = -1e30f;
                if (c0 + 1 > lim1) S[nf][3] = -1e30f;
            }
        }

        float mx0 = -1e30f, mx1 = -1e30f;
#pragma unroll
        for (int nf = 0; nf < 16; ++nf) {
            mx0 = fmaxf(mx0, fmaxf(S[nf][0], S[nf][1]));
            mx1 = fmaxf(mx1, fmaxf(S[nf][2], S[nf][3]));
        }
        mx0 = fmaxf(mx0, __shfl_xor_sync(0xffffffffu, mx0, 1));
        mx0 = fmaxf(mx0, __shfl_xor_sync(0xffffffffu, mx0, 2));
        mx1 = fmaxf(mx1, __shfl_xor_sync(0xffffffffu, mx1, 1));
        mx1 = fmaxf(mx1, __shfl_xor_sync(0xffffffffu, mx1, 2));
        const float mn0 = fmaxf(m_0, mx0), mn1 = fmaxf(m_1, mx1);
        const float f0 = __expf(m_0 - mn0), f1 = __expf(m_1 - mn1);
        m_0 = mn0; m_1 = mn1;

        float rs0 = 0.f, rs1 = 0.f;
#pragma unroll
        for (int nf = 0; nf < 16; ++nf) {
            S[nf][0] = __expf(S[nf][0] - mn0);
            S[nf][1] = __expf(S[nf][1] - mn0);
            S[nf][2] = __expf(S[nf][2] - mn1);
            S[nf][3] = __expf(S[nf][3] - mn1);
            rs0 += S[nf][0] + S[nf][1];
            rs1 += S[nf][2] + S[nf][3];
        }
        rs0 += __shfl_xor_sync(0xffffffffu, rs0, 1);
        rs0 += __shfl_xor_sync(0xffffffffu, rs0, 2);
        rs1 += __shfl_xor_sync(0xffffffffu, rs1, 1);
        rs1 += __shfl_xor_sync(0xffffffffu, rs1, 2);
        l_0 = l_0 * f0 + rs0;
        l_1 = l_1 * f1 + rs1;
#pragma unroll
        for (int nj = 0; nj < 8; ++nj) {
            O[nj][0] *= f0; O[nj][1] *= f0;
            O[nj][2] *= f1; O[nj][3] *= f1;
        }

        const uint32_t kr   = (uint32_t)(((lane & 8) ? 8 : 0) + (lane & 7));
        const uint32_t dsel = (lane & 16) ? 8u : 0u;
#pragma unroll
        for (int t = 0; t < 8; ++t) {
            uint32_t ph[4], pl[4];
            pack_hl(S[2 * t][0],     S[2 * t][1],     ph[0], pl[0]);
            pack_hl(S[2 * t][2],     S[2 * t][3],     ph[1], pl[1]);
            pack_hl(S[2 * t + 1][0], S[2 * t + 1][1], ph[2], pl[2]);
            pack_hl(S[2 * t + 1][2], S[2 * t + 1][3], ph[3], pl[3]);
#pragma unroll
            for (int db = 0; db < 64; db += 16) {
                const uint32_t voff2 = SWZ((uint32_t)((t * 16 + kr) * 128
                                                      + (db + dsel) * 2));
                uint32_t vh[4], vl[4];
                ldmatrix_x4_t(vh[0], vh[1], vh[2], vh[3], VB + voff2);
                ldmatrix_x4_t(vl[0], vl[1], vl[2], vl[3], VB + 16384 + voff2);
                const int oj = db / 8;
                mma16816(O[oj],     ph, vh[0], vh[1]);
                mma16816(O[oj],     ph, vl[0], vl[1]);
                mma16816(O[oj],     pl, vh[0], vh[1]);
                mma16816(O[oj + 1], ph, vh[2], vh[3]);
                mma16816(O[oj + 1], ph, vl[2], vl[3]);
                mma16816(O[oj + 1], pl, vh[2], vh[3]);
            }
        }

        __syncthreads();
        if (kt + 1 < nb) {
            if (kt + 2 < nb) {
                flash_issue_kv(sb + 32768 + (kt & 1) * FL_STAGE, qh, ql,
                               (kt + 2) * 128, koff, voff, tid);
                cp_commit();
                cp_wait<1>();
            } else {
                cp_wait<0>();
            }
            __syncthreads();
        }
    }

    const float inv0 = 1.f / l_0, inv1 = 1.f / l_1;
    const int r0 = m0 + wm + (lane >> 2);
    const int col0 = h * 64 + 2 * (lane & 3);
#pragma unroll
    for (int nj = 0; nj < 8; ++nj) {
        const int col = col0 + nj * 8;
        uint32_t hh, ll;
        pack_hl(O[nj][0] * inv0, O[nj][1] * inv0, hh, ll);
        *(uint32_t*)(yh + (size_t)r0 * CDIM + col) = hh;
        *(uint32_t*)(yl + (size_t)r0 * CDIM + col) = ll;
        pack_hl(O[nj][2] * inv1, O[nj][3] * inv1, hh, ll);
        *(uint32_t*)(yh + (size_t)(r0 + 8) * CDIM + col) = hh;
        *(uint32_t*)(yl + (size_t)(r0 + 8) * CDIM + col) = ll;
    }
}

// ---------------------------------------------------------------------------
extern "C" void kernel_launch(void* const* d_in, const int* in_sizes, int n_in,
                              void* d_out, int out_size)
{
    const float* x      = (const float*)d_in[0];
    const float* cosb   = (const float*)d_in[1];
    const float* sinb   = (const float*)d_in[2];
    const float* W_attn = (const float*)d_in[3];
    const float* b_attn = (const float*)d_in[4];
    const float* W_proj = (const float*)d_in[5];
    const float* b_proj = (const float*)d_in[6];
    float* out = (float*)d_out;

    __nv_bfloat16 *qh, *ql, *xh, *xl, *wah, *wal, *wph, *wpl, *yh, *yl;
    cudaGetSymbolAddress((void**)&qh,  g_qh);
    cudaGetSymbolAddress((void**)&ql,  g_ql);
    cudaGetSymbolAddress((void**)&xh,  g_xh);
    cudaGetSymbolAddress((void**)&xl,  g_xl);
    cudaGetSymbolAddress((void**)&wah, g_wah);
    cudaGetSymbolAddress((void**)&wal, g_wal);
    cudaGetSymbolAddress((void**)&wph, g_wph);
    cudaGetSymbolAddress((void**)&wpl, g_wpl);
    cudaGetSymbolAddress((void**)&yh,  g_yh);
    cudaGetSymbolAddress((void**)&yl,  g_yl);

    cudaFuncSetAttribute(gemm_bf16<QKVD, CDIM, true>,
                         cudaFuncAttributeMaxDynamicSharedMemorySize, GEMM_SMEM_BYTES);
    cudaFuncSetAttribute(gemm_bf16<CDIM, CDIM, false>,
                         cudaFuncAttributeMaxDynamicSharedMemorySize, GEMM_SMEM_BYTES);
    cudaFuncSetAttribute(flash_mma,
                         cudaFuncAttributeMaxDynamicSharedMemorySize, FLASH_SMEM_BYTES);

    // 0) split inputs to bf16 hi/lo
    cvt_hl<<<(TSEQ * CDIM / 2 + 255) / 256, 256>>>(x, xh, xl, TSEQ * CDIM / 2);
    cvt_hl<<<(QKVD * CDIM / 2 + 255) / 256, 256>>>(W_attn, wah, wal, QKVD * CDIM / 2);
    cvt_hl<<<(CDIM * CDIM / 2 + 255) / 256, 256>>>(W_proj, wph, wpl, CDIM * CDIM / 2);

    // 1) QKV GEMM + bias -> hi/lo qkv
    gemm_bf16<QKVD, CDIM, true>
        <<<dim3(QKVD / 128, TSEQ / 128), 256, GEMM_SMEM_BYTES>>>(
            xh, xl, wah, wal, b_attn, nullptr, qh, ql);

    // 2) RoPE in place on hi/lo (scale folded into Q)
    rope_hl<<<TSEQ * 40 / 8, 256>>>(qh, ql, cosb, sinb);

    // 3) causal flash attention -> hi/lo y
    flash_mma<<<dim3(NHEAD, TSEQ / 128), 256, FLASH_SMEM_BYTES>>>(qh, ql, yh, yl);

    // 4) output projection + bias -> fp32 out
    gemm_bf16<CDIM, CDIM, false>
        <<<dim3(CDIM / 128, TSEQ / 128), 256, GEMM_SMEM_BYTES>>>(
            yh, yl, wph, wpl, b_proj, out, nullptr, nullptr);
}